// round 15
// baseline (speedup 1.0000x reference)
#include <cuda_runtime.h>
#include <cuda_bf16.h>
#include <math.h>
#include <stdint.h>

#define Nn 2048
#define Fd 256
#define Hh 8
#define NH (Nn*Hh)
#define ICP 64           // i-chunks for Z partials (colz: 32 rows per chunk)
#define CZ_RPC 32
#define AT_RPC 8         // attnp rows per chunk (grid y = 256)
#define BK 32

// ---------------- scratch (static device globals) ----------------
__device__ float g_eq1[NH];
__device__ float g_eq2[NH];
__device__ float g_rZ[NH];
__device__ float g_P[ICP*NH];                          // Z-partials (4MB)
__device__ float g_Zs[16*NH];                          // zred stage-1 partials (2MB)
__device__ __align__(16) __nv_bfloat16 g_Phi[Nn*Nn];   // P hi [N][N]
__device__ __align__(16) __nv_bfloat16 g_Plo[Nn*Nn];   // P lo
__device__ __align__(16) __nv_bfloat16 g_vThi[Fd*Nn];  // v^T hi [F][N]
__device__ __align__(16) __nv_bfloat16 g_vTlo[Fd*Nn];
__device__ __align__(16) __nv_bfloat16 g_Uhi[Nn*Fd];   // U hi [N][F]
__device__ __align__(16) __nv_bfloat16 g_Ulo[Nn*Fd];
__device__ float g_C[Nn*Nn];
__device__ float g_Sp[32*Nn];                          // LN row-sum partials per 64-col block
__device__ float g_S2p[32*Nn];
__device__ float g_mu[Nn];
__device__ float g_rs[Nn];

// ---------------- mma helpers ----------------
__device__ __forceinline__ uint32_t smem_u32(const void* p) {
    uint32_t a;
    asm("{ .reg .u64 t; cvta.to.shared.u64 t, %1; cvt.u32.u64 %0, t; }" : "=r"(a) : "l"(p));
    return a;
}
__device__ __forceinline__ void ldm4(uint32_t* r, uint32_t addr) {
    asm volatile("ldmatrix.sync.aligned.m8n8.x4.shared.b16 {%0,%1,%2,%3}, [%4];"
        : "=r"(r[0]), "=r"(r[1]), "=r"(r[2]), "=r"(r[3]) : "r"(addr));
}
__device__ __forceinline__ void mma16816(float* c, const uint32_t* a, uint32_t b0, uint32_t b1) {
    asm volatile("mma.sync.aligned.m16n8k16.row.col.f32.bf16.bf16.f32 "
        "{%0,%1,%2,%3}, {%4,%5,%6,%7}, {%8,%9}, {%0,%1,%2,%3};"
        : "+f"(c[0]), "+f"(c[1]), "+f"(c[2]), "+f"(c[3])
        : "r"(a[0]), "r"(a[1]), "r"(a[2]), "r"(a[3]), "r"(b0), "r"(b1));
}

// ---------------- qk projection ----------------
__global__ void qk_kernel(const float* __restrict__ X, const float* __restrict__ Wq,
                          const float* __restrict__ Wk) {
    __shared__ float xs[Fd];
    int i = blockIdx.x;
    int t = threadIdx.x;
    xs[t] = X[i*Fd + t];
    __syncthreads();
    int w = t >> 5, lane = t & 31;
    float qa = 0.f, ka = 0.f;
    #pragma unroll
    for (int c = lane; c < Fd; c += 32) {
        float x = xs[c];
        qa = fmaf(x, Wq[c*Hh + w], qa);
        ka = fmaf(x, Wk[c*Hh + w], ka);
    }
    #pragma unroll
    for (int o = 16; o > 0; o >>= 1) {
        qa += __shfl_down_sync(0xffffffffu, qa, o);
        ka += __shfl_down_sync(0xffffffffu, ka, o);
    }
    if (lane == 0) {
        float qk = (qa + ka) * (0.0625f * 0.3535533905932738f);
        g_eq1[i*Hh + w] = __expf(qk);
        g_eq2[i*Hh + w] = __expf(0.2f * qk);
    }
}

// ---------------- v = X @ Wv / 16, fused transpose + hi/lo split ----------------
__global__ void gemm_v_kernel(const float* __restrict__ X, const float* __restrict__ Wv) {
    __shared__ float As[16][64];
    __shared__ float Bs[16][64];
    __shared__ float vs[64][65];
    int tid = threadIdx.x;
    int bi = blockIdx.y * 64;
    int bc = blockIdx.x * 64;
    int arow = tid >> 2,  acol = (tid & 3)  << 2;
    int brow = tid >> 4,  bcol = (tid & 15) << 2;
    int ty   = tid >> 4,  tx   = tid & 15;
    float acc[4][4] = {};
    for (int k0 = 0; k0 < Fd; k0 += 16) {
        float4 a = *(const float4*)&X[(size_t)(bi + arow)*Fd + k0 + acol];
        float4 b = *(const float4*)&Wv[(size_t)(k0 + brow)*Fd + bc + bcol];
        As[acol+0][arow] = a.x; As[acol+1][arow] = a.y;
        As[acol+2][arow] = a.z; As[acol+3][arow] = a.w;
        *(float4*)&Bs[brow][bcol] = b;
        __syncthreads();
        #pragma unroll
        for (int kk = 0; kk < 16; kk++) {
            float ar[4], br[4];
            *(float4*)ar = *(const float4*)&As[kk][ty*4];
            *(float4*)br = *(const float4*)&Bs[kk][tx*4];
            #pragma unroll
            for (int r = 0; r < 4; r++)
                #pragma unroll
                for (int c = 0; c < 4; c++)
                    acc[r][c] = fmaf(ar[r], br[c], acc[r][c]);
        }
        __syncthreads();
    }
    #pragma unroll
    for (int r = 0; r < 4; r++)
        #pragma unroll
        for (int c = 0; c < 4; c++)
            vs[ty*4 + r][tx*4 + c] = acc[r][c] * 0.0625f;
    __syncthreads();
    #pragma unroll
    for (int r = 0; r < 4; r++) {
        int wf = ty*4 + r;
        __nv_bfloat16 hi4[4], lo4[4];
        #pragma unroll
        for (int c = 0; c < 4; c++) {
            float x = vs[tx*4 + c][wf];
            hi4[c] = __float2bfloat16(x);
            lo4[c] = __float2bfloat16(x - __bfloat162float(hi4[c]));
        }
        size_t off = (size_t)(bc + wf)*Nn + bi + tx*4;
        *(uint2*)&g_vThi[off] = *(uint2*)hi4;
        *(uint2*)&g_vTlo[off] = *(uint2*)lo4;
    }
}

// ---------------- pass B: column softmax denominators ----------------
__global__ void colz_kernel(const float* __restrict__ bond, const float* __restrict__ dist,
                            const float* __restrict__ deg, const float* __restrict__ pwb,
                            const float* __restrict__ pwbc, const float* __restrict__ pwg) {
    __shared__ float2 se[CZ_RPC*Hh];
    int tid = threadIdx.x;
    int j = blockIdx.x*128 + tid;
    int i0 = blockIdx.y*CZ_RPC;
    for (int t = tid; t < CZ_RPC*Hh; t += 128)
        se[t] = make_float2(g_eq1[i0*Hh + t], g_eq2[i0*Hh + t]);
    __syncthreads();
    float cb = pwb[0]*pwbc[0], wg = pwg[0];
    float z[Hh];
    #pragma unroll
    for (int h = 0; h < Hh; h++) z[h] = 0.f;
    #pragma unroll 4
    for (int ii = 0; ii < CZ_RPC; ii++) {
        size_t idx = (size_t)(i0+ii)*Nn + j;
        float dg = deg[idx], bd = bond[idx], ds = dist[idx];
        float e = fmaf(bd, cb, ds*wg);
        float f = dg > 0.f ? 1.f : 0.f;
        float e2 = __expf(0.2f*e) * f;
        float e2sq = e2*e2;
        float e1 = e2sq*e2sq*e2;   // exp(e)*f
        #pragma unroll
        for (int h = 0; h < Hh; h++) {
            float2 s12 = se[ii*Hh + h];
            z[h] += fmaxf(s12.x*e1, s12.y*e2);
        }
    }
    float* zp = &g_P[(size_t)blockIdx.y*NH + (size_t)j*Hh];
    *(float4*)&zp[0] = make_float4(z[0], z[1], z[2], z[3]);
    *(float4*)&zp[4] = make_float4(z[4], z[5], z[6], z[7]);
}

// ---------------- zred: two-stage deterministic reduction (1024 + 64 CTAs) ----------------
__global__ void zred1_kernel() {
    int t = blockIdx.x*256 + threadIdx.x;   // < NH
    int c0 = blockIdx.y*4;
    float s = (g_P[(size_t)(c0+0)*NH + t] + g_P[(size_t)(c0+1)*NH + t])
            + (g_P[(size_t)(c0+2)*NH + t] + g_P[(size_t)(c0+3)*NH + t]);
    g_Zs[(size_t)blockIdx.y*NH + t] = s;
}
__global__ void zred2_kernel() {
    int t = blockIdx.x*256 + threadIdx.x;   // < NH
    float s = 0.f;
    #pragma unroll
    for (int c = 0; c < 16; c++) s += g_Zs[(size_t)c*NH + t];
    g_rZ[t] = 1.f / s;
}

// ---------------- pass C: P -> bf16 hi/lo (2 cols/thread, 256 threads) ----------------
__global__ void __launch_bounds__(256) attnp_kernel(
        const float* __restrict__ bond, const float* __restrict__ dist,
        const float* __restrict__ deg, const float* __restrict__ pwb,
        const float* __restrict__ pwbc, const float* __restrict__ pwg) {
    __shared__ float2 se[AT_RPC*Hh];
    int tid = threadIdx.x;
    int j = blockIdx.x*512 + tid*2;
    int i0 = blockIdx.y*AT_RPC;
    if (tid < AT_RPC*Hh) se[tid] = make_float2(g_eq1[i0*Hh + tid], g_eq2[i0*Hh + tid]);
    __syncthreads();
    float rz[2][Hh];
    #pragma unroll
    for (int l = 0; l < 2; l++)
        #pragma unroll
        for (int h = 0; h < Hh; h += 4)
            *(float4*)&rz[l][h] = *(const float4*)&g_rZ[(size_t)(j+l)*Hh + h];
    float cb = pwb[0]*pwbc[0], wg = pwg[0];
    #pragma unroll
    for (int ii = 0; ii < AT_RPC; ii++) {
        size_t idx = (size_t)(i0+ii)*Nn + j;
        float2 dg = *(const float2*)&deg[idx];
        float2 bd = *(const float2*)&bond[idx];
        float2 ds = *(const float2*)&dist[idx];
        const float* dgp = &dg.x; const float* bdp = &bd.x; const float* dsp = &ds.x;
        float p[2] = {0.f, 0.f};
        float E1[2], E2[2];
        #pragma unroll
        for (int l = 0; l < 2; l++) {
            float e = fmaf(bdp[l], cb, dsp[l]*wg);
            float f = dgp[l] > 0.f ? 1.f : 0.f;
            float e2 = __expf(0.2f*e) * f;
            float e2sq = e2*e2;
            E2[l] = e2;
            E1[l] = e2sq*e2sq*e2;
        }
        #pragma unroll
        for (int h = 0; h < Hh; h++) {
            float2 s12 = se[ii*Hh + h];
            #pragma unroll
            for (int l = 0; l < 2; l++)
                p[l] = fmaf(fmaxf(s12.x*E1[l], s12.y*E2[l]), rz[l][h], p[l]);
        }
        __nv_bfloat16 hi2[2], lo2[2];
        #pragma unroll
        for (int l = 0; l < 2; l++) {
            float pv = p[l] * 0.125f;
            hi2[l] = __float2bfloat16(pv);
            lo2[l] = __float2bfloat16(pv - __bfloat162float(hi2[l]));
        }
        *(uint32_t*)&g_Phi[idx] = *(uint32_t*)hi2;
        *(uint32_t*)&g_Plo[idx] = *(uint32_t*)lo2;
    }
}

// ---------------- HMMA GEMM: U = elu(P @ v), 32x64 tiles, full-K (256 CTAs) ----------------
#define PVA_TILE (32*80)      // 2560 B
#define PVB_TILE (64*80)      // 5120 B
#define PV_AHI   0
#define PV_ALO   (PVA_TILE)
#define PV_BHI   (2*PVA_TILE)
#define PV_BLO   (2*PVA_TILE + PVB_TILE)
#define PV_STAGE (2*PVA_TILE + 2*PVB_TILE)   // 15360

__global__ void __launch_bounds__(256) gemm_pv_mma(float* __restrict__ outU) {
    __shared__ __align__(16) char smem[2*PV_STAGE];
    uint32_t sb = smem_u32(smem);
    const int tid = threadIdx.x, lane = tid & 31, wid = tid >> 5;
    const int mbase = (wid & 1)*16, nbase = (wid >> 1)*16;   // 2x4 warps, 16x16 warp tile
    const int bi = blockIdx.y*32, bc = blockIdx.x*64;
    const int arow = tid >> 3, ach = (tid & 7) & 3;          // tid<128: A loads
    const int aok = (tid < 128) && ((tid & 7) < 4) ? 1 : 1;  // see mapping below
    const int brow = tid >> 2, bch = tid & 3;                // all threads: B loads
    const int NT = Nn/BK;                                    // 64

    // A load mapping: 128 uint4 per matrix; threads 0..127 each take one (row=tid>>2, ch=tid&3)
    const int Ar = tid >> 2, Ac = tid & 3;
    const bool doA = (tid < 128);

    float acc[2][4] = {};
    uint4 pa0, pa1, pb0, pb1;
    {
        int k0 = 0;
        if (doA) {
            pa0 = *(const uint4*)&g_Phi[(size_t)(bi + Ar)*Nn + k0 + Ac*8];
            pa1 = *(const uint4*)&g_Plo[(size_t)(bi + Ar)*Nn + k0 + Ac*8];
            *(uint4*)(smem + PV_AHI + Ar*80 + Ac*16) = pa0;
            *(uint4*)(smem + PV_ALO + Ar*80 + Ac*16) = pa1;
        }
        pb0 = *(const uint4*)&g_vThi[(size_t)(bc + brow)*Nn + k0 + bch*8];
        pb1 = *(const uint4*)&g_vTlo[(size_t)(bc + brow)*Nn + k0 + bch*8];
        *(uint4*)(smem + PV_BHI + brow*80 + bch*16) = pb0;
        *(uint4*)(smem + PV_BLO + brow*80 + bch*16) = pb1;
    }
    __syncthreads();

    for (int kt = 0; kt < NT; kt++) {
        int cur = kt & 1, nxt = cur ^ 1;
        if (kt + 1 < NT) {
            int k0 = (kt+1)*BK;
            if (doA) {
                pa0 = *(const uint4*)&g_Phi[(size_t)(bi + Ar)*Nn + k0 + Ac*8];
                pa1 = *(const uint4*)&g_Plo[(size_t)(bi + Ar)*Nn + k0 + Ac*8];
            }
            pb0 = *(const uint4*)&g_vThi[(size_t)(bc + brow)*Nn + k0 + bch*8];
            pb1 = *(const uint4*)&g_vTlo[(size_t)(bc + brow)*Nn + k0 + bch*8];
        }
        uint32_t base = sb + cur*PV_STAGE;
        #pragma unroll
        for (int kk = 0; kk < 2; kk++) {
            uint32_t rsel = lane & 15;
            uint32_t csel = (kk*16 + ((lane >> 4) << 3)) * 2;
            uint32_t ah[4], al[4], bh[4], bl[4];
            ldm4(ah, base + PV_AHI + (mbase + rsel)*80 + csel);
            ldm4(al, base + PV_ALO + (mbase + rsel)*80 + csel);
            ldm4(bh, base + PV_BHI + (nbase + rsel)*80 + csel);
            ldm4(bl, base + PV_BLO + (nbase + rsel)*80 + csel);
            #pragma unroll
            for (int nt = 0; nt < 2; nt++) {
                mma16816(acc[nt], ah, bh[nt], bh[2+nt]);
                mma16816(acc[nt], ah, bl[nt], bl[2+nt]);
                mma16816(acc[nt], al, bh[nt], bh[2+nt]);
            }
        }
        if (kt + 1 < NT) {
            char* dsts = smem + nxt*PV_STAGE;
            if (doA) {
                *(uint4*)(dsts + PV_AHI + Ar*80 + Ac*16) = pa0;
                *(uint4*)(dsts + PV_ALO + Ar*80 + Ac*16) = pa1;
            }
            *(uint4*)(dsts + PV_BHI + brow*80 + bch*16) = pb0;
            *(uint4*)(dsts + PV_BLO + brow*80 + bch*16) = pb1;
        }
        __syncthreads();
    }

    // epilogue: elu + fp32 out + bf16 hi/lo split
    #pragma unroll
    for (int nt = 0; nt < 2; nt++) {
        int c0 = bc + nbase + nt*8 + (lane & 3)*2;
        #pragma unroll
        for (int half = 0; half < 2; half++) {
            int rr = bi + mbase + (lane >> 2) + half*8;
            float v0 = acc[nt][half*2], v1 = acc[nt][half*2 + 1];
            float e0 = v0 > 0.f ? v0 : expm1f(v0);
            float e1 = v1 > 0.f ? v1 : expm1f(v1);
            *(float2*)&outU[(size_t)rr*Fd + c0] = make_float2(e0, e1);
            __nv_bfloat16 h0 = __float2bfloat16(e0), h1 = __float2bfloat16(e1);
            __nv_bfloat16 l0 = __float2bfloat16(e0 - __bfloat162float(h0));
            __nv_bfloat16 l1 = __float2bfloat16(e1 - __bfloat162float(h1));
            __nv_bfloat162 hv; hv.x = h0; hv.y = h1;
            __nv_bfloat162 lv; lv.x = l0; lv.y = l1;
            *(__nv_bfloat162*)&g_Uhi[(size_t)rr*Fd + c0] = hv;
            *(__nv_bfloat162*)&g_Ulo[(size_t)rr*Fd + c0] = lv;
        }
    }
}

// ---------------- HMMA GEMM: sim = U U^T, 64x64 tiles (528 CTAs), fused epilogue ----------------
#define SM_TILE  (64*80)
#define SM_AHI   0
#define SM_ALO   (SM_TILE)
#define SM_BHI   (2*SM_TILE)
#define SM_BLO   (3*SM_TILE)
#define SM_STAGE (4*SM_TILE)  // 20480

__global__ void __launch_bounds__(256) sim_mma(const float* __restrict__ dist,
                                               const float* __restrict__ deg) {
    int t = blockIdx.x;
    int a = 0;
    while (t >= 32 - a) { t -= 32 - a; a++; }
    int b = a + t;                        // a <= b over 32x32 64-blocks
    int bi = a*64, bj = b*64;

    __shared__ __align__(16) char smem[2*SM_STAGE];
    uint32_t sb = smem_u32(smem);
    const int tid = threadIdx.x, lane = tid & 31, wid = tid >> 5;
    const int mbase = (wid & 3)*16, nbase = (wid >> 2)*32;
    const int row = tid >> 2, ch = tid & 3;
    const int NT = Fd/BK;                 // 8

    float acc[4][4] = {};
    uint4 pa0, pa1, pb0, pb1;
    {
        int k0 = ch*8;
        pa0 = *(const uint4*)&g_Uhi[(size_t)(bi + row)*Fd + k0];
        pa1 = *(const uint4*)&g_Ulo[(size_t)(bi + row)*Fd + k0];
        pb0 = *(const uint4*)&g_Uhi[(size_t)(bj + row)*Fd + k0];
        pb1 = *(const uint4*)&g_Ulo[(size_t)(bj + row)*Fd + k0];
        *(uint4*)(smem + SM_AHI + row*80 + ch*16) = pa0;
        *(uint4*)(smem + SM_ALO + row*80 + ch*16) = pa1;
        *(uint4*)(smem + SM_BHI + row*80 + ch*16) = pb0;
        *(uint4*)(smem + SM_BLO + row*80 + ch*16) = pb1;
    }
    __syncthreads();

    for (int kt = 0; kt < NT; kt++) {
        int cur = kt & 1, nxt = cur ^ 1;
        if (kt + 1 < NT) {
            int k0 = (kt+1)*BK + ch*8;
            pa0 = *(const uint4*)&g_Uhi[(size_t)(bi + row)*Fd + k0];
            pa1 = *(const uint4*)&g_Ulo[(size_t)(bi + row)*Fd + k0];
            pb0 = *(const uint4*)&g_Uhi[(size_t)(bj + row)*Fd + k0];
            pb1 = *(const uint4*)&g_Ulo[(size_t)(bj + row)*Fd + k0];
        }
        uint32_t base = sb + cur*SM_STAGE;
        #pragma unroll
        for (int kk = 0; kk < 2; kk++) {
            uint32_t rsel = lane & 15;
            uint32_t csel = (kk*16 + ((lane >> 4) << 3)) * 2;
            uint32_t ah[4], al[4], bh[2][4], bl[2][4];
            ldm4(ah, base + SM_AHI + (mbase + rsel)*80 + csel);
            ldm4(al, base + SM_ALO + (mbase + rsel)*80 + csel);
            #pragma unroll
            for (int ck = 0; ck < 2; ck++) {
                uint32_t ro = (nbase + ck*16 + rsel)*80 + csel;
                ldm4(bh[ck], base + SM_BHI + ro);
                ldm4(bl[ck], base + SM_BLO + ro);
            }
            #pragma unroll
            for (int nt = 0; nt < 4; nt++) {
                int ck = nt >> 1, pr = nt & 1;
                mma16816(acc[nt], ah, bh[ck][pr], bh[ck][2+pr]);
                mma16816(acc[nt], ah, bl[ck][pr], bl[ck][2+pr]);
                mma16816(acc[nt], al, bh[ck][pr], bh[ck][2+pr]);
            }
        }
        if (kt + 1 < NT) {
            *(uint4*)(smem + nxt*SM_STAGE + SM_AHI + row*80 + ch*16) = pa0;
            *(uint4*)(smem + nxt*SM_STAGE + SM_ALO + row*80 + ch*16) = pa1;
            *(uint4*)(smem + nxt*SM_STAGE + SM_BHI + row*80 + ch*16) = pb0;
            *(uint4*)(smem + nxt*SM_STAGE + SM_BLO + row*80 + ch*16) = pb1;
        }
        __syncthreads();
    }

    // stage sigmoid(sim) into smem [64][65] floats
    float* st = (float*)smem;
    #pragma unroll
    for (int nt = 0; nt < 4; nt++) {
        int c0 = nbase + nt*8 + (lane & 3)*2;
        int r0 = mbase + (lane >> 2);
        st[r0*65 + c0]       = 1.f / (1.f + __expf(-acc[nt][0]));
        st[r0*65 + c0 + 1]   = 1.f / (1.f + __expf(-acc[nt][1]));
        st[(r0+8)*65 + c0]   = 1.f / (1.f + __expf(-acc[nt][2]));
        st[(r0+8)*65 + c0+1] = 1.f / (1.f + __expf(-acc[nt][3]));
    }
    __syncthreads();
    // direct block C[bi+row, bj+col]; LN partials for col-block b, rows bi..
    #pragma unroll
    for (int rep = 0; rep < 2; rep++) {
        int lin = rep*256 + tid;
        int rr = lin >> 3;
        int cb = (lin & 7) << 3;
        size_t idx = (size_t)(bi + rr)*Nn + bj + cb;
        float4 d0 = *(const float4*)&dist[idx];
        float4 d1 = *(const float4*)&dist[idx + 4];
        float4 m0 = *(const float4*)&deg[idx];
        float4 m1 = *(const float4*)&deg[idx + 4];
        const float* sr = &st[rr*65 + cb];
        float4 o0 = make_float4(sr[0]*(-d0.x)*m0.x, sr[1]*(-d0.y)*m0.y,
                                sr[2]*(-d0.z)*m0.z, sr[3]*(-d0.w)*m0.w);
        float4 o1 = make_float4(sr[4]*(-d1.x)*m1.x, sr[5]*(-d1.y)*m1.y,
                                sr[6]*(-d1.z)*m1.z, sr[7]*(-d1.w)*m1.w);
        *(float4*)&g_C[idx]     = o0;
        *(float4*)&g_C[idx + 4] = o1;
        float s  = ((o0.x+o0.y)+(o0.z+o0.w)) + ((o1.x+o1.y)+(o1.z+o1.w));
        float s2 = fmaf(o0.x,o0.x, fmaf(o0.y,o0.y, fmaf(o0.z,o0.z, fmaf(o0.w,o0.w,
                   fmaf(o1.x,o1.x, fmaf(o1.y,o1.y, fmaf(o1.z,o1.z, o1.w*o1.w)))))));
        #pragma unroll
        for (int off = 4; off > 0; off >>= 1) {
            s  += __shfl_down_sync(0xffffffffu, s,  off, 8);
            s2 += __shfl_down_sync(0xffffffffu, s2, off, 8);
        }
        if ((tid & 7) == 0) {
            g_Sp[(size_t)b*Nn + bi + rr]  = s;
            g_S2p[(size_t)b*Nn + bi + rr] = s2;
        }
    }
    // mirror block C[bj+row, bi+col]; LN partials for col-block a, rows bj..
    if (a != b) {
        #pragma unroll
        for (int rep = 0; rep < 2; rep++) {
            int lin = rep*256 + tid;
            int rr = lin >> 3;
            int cb = (lin & 7) << 3;
            size_t idx = (size_t)(bj + rr)*Nn + bi + cb;
            float4 d0 = *(const float4*)&dist[idx];
            float4 d1 = *(const float4*)&dist[idx + 4];
            float4 m0 = *(const float4*)&deg[idx];
            float4 m1 = *(const float4*)&deg[idx + 4];
            float sv[8];
            #pragma unroll
            for (int k = 0; k < 8; k++) sv[k] = st[(cb + k)*65 + rr];
            float4 o0 = make_float4(sv[0]*(-d0.x)*m0.x, sv[1]*(-d0.y)*m0.y,
                                    sv[2]*(-d0.z)*m0.z, sv[3]*(-d0.w)*m0.w);
            float4 o1 = make_float4(sv[4]*(-d1.x)*m1.x, sv[5]*(-d1.y)*m1.y,
                                    sv[6]*(-d1.z)*m1.z, sv[7]*(-d1.w)*m1.w);
            *(float4*)&g_C[idx]     = o0;
            *(float4*)&g_C[idx + 4] = o1;
            float s  = ((o0.x+o0.y)+(o0.z+o0.w)) + ((o1.x+o1.y)+(o1.z+o1.w));
            float s2 = fmaf(o0.x,o0.x, fmaf(o0.y,o0.y, fmaf(o0.z,o0.z, fmaf(o0.w,o0.w,
                       fmaf(o1.x,o1.x, fmaf(o1.y,o1.y, fmaf(o1.z,o1.z, o1.w*o1.w)))))));
            #pragma unroll
            for (int off = 4; off > 0; off >>= 1) {
                s  += __shfl_down_sync(0xffffffffu, s,  off, 8);
                s2 += __shfl_down_sync(0xffffffffu, s2, off, 8);
            }
            if ((tid & 7) == 0) {
                g_Sp[(size_t)a*Nn + bj + rr]  = s;
                g_S2p[(size_t)a*Nn + bj + rr] = s2;
            }
        }
    }
}

// ---------------- finish LN stats from partials ----------------
__global__ void rn_stats2_kernel() {
    int i = blockIdx.x*256 + threadIdx.x;   // < Nn
    float s = 0.f, s2 = 0.f;
    #pragma unroll
    for (int c = 0; c < 32; c++) {
        s  += g_Sp[(size_t)c*Nn + i];
        s2 += g_S2p[(size_t)c*Nn + i];
    }
    float mean = s * (1.f/Nn);
    float var  = s2 * (1.f/Nn) - mean*mean;
    g_mu[i] = mean;
    g_rs[i] = rsqrtf(var + 1e-5f);
}

// ---------------- out = norm(C) + norm(C)^T  (symmetric: compute once, write twice) ----------------
__global__ void symadd_kernel(float* __restrict__ outC) {
    int t = blockIdx.x;
    int a = 0;
    while (t >= 64 - a) { t -= 64 - a; a++; }
    int b = a + t;   // a <= b, 32x32 blocks
    __shared__ float tA[32][33], tB[32][33], tV[32][33];
    int tx = threadIdx.x, ty = threadIdx.y;
    #pragma unroll
    for (int r = 0; r < 32; r += 8) {
        tA[ty + r][tx] = g_C[(size_t)(a*32 + ty + r)*Nn + b*32 + tx];
        tB[ty + r][tx] = g_C[(size_t)(b*32 + ty + r)*Nn + a*32 + tx];
    }
    int j = b*32 + tx;
    float muj = g_mu[j], rsj = g_rs[j];
    __syncthreads();
    #pragma unroll
    for (int r = 0; r < 32; r += 8) {
        int i = a*32 + ty + r;
        float v = (tA[ty + r][tx] - g_mu[i])*g_rs[i] + (tB[tx][ty + r] - muj)*rsj;
        outC[(size_t)i*Nn + j] = v;
        tV[ty + r][tx] = v;
    }
    if (a != b) {
        __syncthreads();
        #pragma unroll
        for (int r = 0; r < 32; r += 8)
            outC[(size_t)(b*32 + ty + r)*Nn + a*32 + tx] = tV[tx][ty + r];
    }
}

extern "C" void kernel_launch(void* const* d_in, const int* in_sizes, int n_in,
                              void* d_out, int out_size) {
    const float* X    = (const float*)d_in[0];
    const float* dist = (const float*)d_in[1];
    const float* bond = (const float*)d_in[2];
    const float* deg  = (const float*)d_in[4];
    const float* Wq   = (const float*)d_in[5];
    const float* Wk   = (const float*)d_in[6];
    const float* Wv   = (const float*)d_in[7];
    const float* wb   = (const float*)d_in[8];
    const float* wbc  = (const float*)d_in[9];
    const float* wg   = (const float*)d_in[10];
    float* out  = (float*)d_out;
    float* outU = out;
    float* outC = out + Nn*Fd;

    // side stream (capture-safe fork/join): gemm_v runs concurrently with the
    // attention chain; it is only needed by gemm_pv_mma.
    cudaStream_t s2;
    cudaStreamCreateWithFlags(&s2, cudaStreamNonBlocking);
    cudaEvent_t evFork, evJoin;
    cudaEventCreateWithFlags(&evFork, cudaEventDisableTiming);
    cudaEventCreateWithFlags(&evJoin, cudaEventDisableTiming);

    qk_kernel<<<Nn, 256>>>(X, Wq, Wk);
    cudaEventRecord(evFork, 0);
    cudaStreamWaitEvent(s2, evFork, 0);
    gemm_v_kernel<<<dim3(Fd/64, Nn/64), 256, 0, s2>>>(X, Wv);
    cudaEventRecord(evJoin, s2);

    colz_kernel<<<dim3(16, ICP), 128>>>(bond, dist, deg, wb, wbc, wg);
    zred1_kernel<<<dim3(NH/256, 16), 256>>>();
    zred2_kernel<<<NH/256, 256>>>();
    attnp_kernel<<<dim3(4, 256), 256>>>(bond, dist, deg, wb, wbc, wg);
    cudaStreamWaitEvent(0, evJoin, 0);
    gemm_pv_mma<<<dim3(Fd/64, Nn/32), 256>>>(outU);
    sim_mma<<<32*33/2, 256>>>(dist, deg);
    rn_stats2_kernel<<<Nn/256, 256>>>();
    symadd_kernel<<<64*65/2, dim3(32, 8)>>>(outC);

    cudaEventDestroy(evFork);
    cudaEventDestroy(evJoin);
    cudaStreamDestroy(s2);
}

// round 16
// speedup vs baseline: 1.0662x; 1.0662x over previous
#include <cuda_runtime.h>
#include <cuda_bf16.h>
#include <math.h>
#include <stdint.h>

#define Nn 2048
#define Fd 256
#define Hh 8
#define NH (Nn*Hh)
#define ICP 64           // i-chunks for Z partials (colz: 32 rows per chunk)
#define CZ_RPC 32
#define AT_RPC 8         // attnp rows per chunk (grid y = 256)
#define BK 32

// ---------------- scratch (static device globals) ----------------
__device__ float g_eq1[NH];
__device__ float g_eq2[NH];
__device__ float g_rZ[NH];
__device__ float g_P[ICP*NH];                          // Z-partials (4MB)
__device__ float g_Zs[16*NH];                          // zred stage-1 partials (2MB)
__device__ __align__(16) __nv_bfloat16 g_Phi[Nn*Nn];   // P hi [N][N]
__device__ __align__(16) __nv_bfloat16 g_Plo[Nn*Nn];   // P lo
__device__ __align__(16) __nv_bfloat16 g_vThi[Fd*Nn];  // v^T hi [F][N]
__device__ __align__(16) __nv_bfloat16 g_vTlo[Fd*Nn];
__device__ __align__(16) __nv_bfloat16 g_Uhi[Nn*Fd];   // U hi [N][F]
__device__ __align__(16) __nv_bfloat16 g_Ulo[Nn*Fd];
__device__ float g_C[Nn*Nn];
__device__ float g_Sp[32*Nn];                          // LN row-sum partials per 64-col block
__device__ float g_S2p[32*Nn];
__device__ float g_mu[Nn];
__device__ float g_rs[Nn];

// ---------------- mma helpers ----------------
__device__ __forceinline__ uint32_t smem_u32(const void* p) {
    uint32_t a;
    asm("{ .reg .u64 t; cvta.to.shared.u64 t, %1; cvt.u32.u64 %0, t; }" : "=r"(a) : "l"(p));
    return a;
}
__device__ __forceinline__ void ldm4(uint32_t* r, uint32_t addr) {
    asm volatile("ldmatrix.sync.aligned.m8n8.x4.shared.b16 {%0,%1,%2,%3}, [%4];"
        : "=r"(r[0]), "=r"(r[1]), "=r"(r[2]), "=r"(r[3]) : "r"(addr));
}
__device__ __forceinline__ void mma16816(float* c, const uint32_t* a, uint32_t b0, uint32_t b1) {
    asm volatile("mma.sync.aligned.m16n8k16.row.col.f32.bf16.bf16.f32 "
        "{%0,%1,%2,%3}, {%4,%5,%6,%7}, {%8,%9}, {%0,%1,%2,%3};"
        : "+f"(c[0]), "+f"(c[1]), "+f"(c[2]), "+f"(c[3])
        : "r"(a[0]), "r"(a[1]), "r"(a[2]), "r"(a[3]), "r"(b0), "r"(b1));
}

// ---------------- qk projection ----------------
__global__ void qk_kernel(const float* __restrict__ X, const float* __restrict__ Wq,
                          const float* __restrict__ Wk) {
    __shared__ float xs[Fd];
    int i = blockIdx.x;
    int t = threadIdx.x;
    xs[t] = X[i*Fd + t];
    __syncthreads();
    int w = t >> 5, lane = t & 31;
    float qa = 0.f, ka = 0.f;
    #pragma unroll
    for (int c = lane; c < Fd; c += 32) {
        float x = xs[c];
        qa = fmaf(x, Wq[c*Hh + w], qa);
        ka = fmaf(x, Wk[c*Hh + w], ka);
    }
    #pragma unroll
    for (int o = 16; o > 0; o >>= 1) {
        qa += __shfl_down_sync(0xffffffffu, qa, o);
        ka += __shfl_down_sync(0xffffffffu, ka, o);
    }
    if (lane == 0) {
        float qk = (qa + ka) * (0.0625f * 0.3535533905932738f);
        g_eq1[i*Hh + w] = __expf(qk);
        g_eq2[i*Hh + w] = __expf(0.2f * qk);
    }
}

// ---------------- v = X @ Wv / 16, fused transpose + hi/lo split ----------------
__global__ void gemm_v_kernel(const float* __restrict__ X, const float* __restrict__ Wv) {
    __shared__ float As[16][64];
    __shared__ float Bs[16][64];
    __shared__ float vs[64][65];
    int tid = threadIdx.x;
    int bi = blockIdx.y * 64;
    int bc = blockIdx.x * 64;
    int arow = tid >> 2,  acol = (tid & 3)  << 2;
    int brow = tid >> 4,  bcol = (tid & 15) << 2;
    int ty   = tid >> 4,  tx   = tid & 15;
    float acc[4][4] = {};
    for (int k0 = 0; k0 < Fd; k0 += 16) {
        float4 a = *(const float4*)&X[(size_t)(bi + arow)*Fd + k0 + acol];
        float4 b = *(const float4*)&Wv[(size_t)(k0 + brow)*Fd + bc + bcol];
        As[acol+0][arow] = a.x; As[acol+1][arow] = a.y;
        As[acol+2][arow] = a.z; As[acol+3][arow] = a.w;
        *(float4*)&Bs[brow][bcol] = b;
        __syncthreads();
        #pragma unroll
        for (int kk = 0; kk < 16; kk++) {
            float ar[4], br[4];
            *(float4*)ar = *(const float4*)&As[kk][ty*4];
            *(float4*)br = *(const float4*)&Bs[kk][tx*4];
            #pragma unroll
            for (int r = 0; r < 4; r++)
                #pragma unroll
                for (int c = 0; c < 4; c++)
                    acc[r][c] = fmaf(ar[r], br[c], acc[r][c]);
        }
        __syncthreads();
    }
    #pragma unroll
    for (int r = 0; r < 4; r++)
        #pragma unroll
        for (int c = 0; c < 4; c++)
            vs[ty*4 + r][tx*4 + c] = acc[r][c] * 0.0625f;
    __syncthreads();
    #pragma unroll
    for (int r = 0; r < 4; r++) {
        int wf = ty*4 + r;
        __nv_bfloat16 hi4[4], lo4[4];
        #pragma unroll
        for (int c = 0; c < 4; c++) {
            float x = vs[tx*4 + c][wf];
            hi4[c] = __float2bfloat16(x);
            lo4[c] = __float2bfloat16(x - __bfloat162float(hi4[c]));
        }
        size_t off = (size_t)(bc + wf)*Nn + bi + tx*4;
        *(uint2*)&g_vThi[off] = *(uint2*)hi4;
        *(uint2*)&g_vTlo[off] = *(uint2*)lo4;
    }
}

// ---------------- pass B: column softmax denominators ----------------
__global__ void colz_kernel(const float* __restrict__ bond, const float* __restrict__ dist,
                            const float* __restrict__ deg, const float* __restrict__ pwb,
                            const float* __restrict__ pwbc, const float* __restrict__ pwg) {
    __shared__ float2 se[CZ_RPC*Hh];
    int tid = threadIdx.x;
    int j = blockIdx.x*128 + tid;
    int i0 = blockIdx.y*CZ_RPC;
    for (int t = tid; t < CZ_RPC*Hh; t += 128)
        se[t] = make_float2(g_eq1[i0*Hh + t], g_eq2[i0*Hh + t]);
    __syncthreads();
    float cb = pwb[0]*pwbc[0], wg = pwg[0];
    float z[Hh];
    #pragma unroll
    for (int h = 0; h < Hh; h++) z[h] = 0.f;
    #pragma unroll 4
    for (int ii = 0; ii < CZ_RPC; ii++) {
        size_t idx = (size_t)(i0+ii)*Nn + j;
        float dg = deg[idx], bd = bond[idx], ds = dist[idx];
        float e = fmaf(bd, cb, ds*wg);
        float f = dg > 0.f ? 1.f : 0.f;
        float e2 = __expf(0.2f*e) * f;
        float e2sq = e2*e2;
        float e1 = e2sq*e2sq*e2;   // exp(e)*f
        #pragma unroll
        for (int h = 0; h < Hh; h++) {
            float2 s12 = se[ii*Hh + h];
            z[h] += fmaxf(s12.x*e1, s12.y*e2);
        }
    }
    float* zp = &g_P[(size_t)blockIdx.y*NH + (size_t)j*Hh];
    *(float4*)&zp[0] = make_float4(z[0], z[1], z[2], z[3]);
    *(float4*)&zp[4] = make_float4(z[4], z[5], z[6], z[7]);
}

// ---------------- zred: two-stage deterministic reduction (1024 + 64 CTAs) ----------------
__global__ void zred1_kernel() {
    int t = blockIdx.x*256 + threadIdx.x;   // < NH
    int c0 = blockIdx.y*4;
    float s = (g_P[(size_t)(c0+0)*NH + t] + g_P[(size_t)(c0+1)*NH + t])
            + (g_P[(size_t)(c0+2)*NH + t] + g_P[(size_t)(c0+3)*NH + t]);
    g_Zs[(size_t)blockIdx.y*NH + t] = s;
}
__global__ void zred2_kernel() {
    int t = blockIdx.x*256 + threadIdx.x;   // < NH
    float s = 0.f;
    #pragma unroll
    for (int c = 0; c < 16; c++) s += g_Zs[(size_t)c*NH + t];
    g_rZ[t] = 1.f / s;
}

// ---------------- pass C: P -> bf16 hi/lo (2 cols/thread, 256 threads) ----------------
__global__ void __launch_bounds__(256) attnp_kernel(
        const float* __restrict__ bond, const float* __restrict__ dist,
        const float* __restrict__ deg, const float* __restrict__ pwb,
        const float* __restrict__ pwbc, const float* __restrict__ pwg) {
    __shared__ float2 se[AT_RPC*Hh];
    int tid = threadIdx.x;
    int j = blockIdx.x*512 + tid*2;
    int i0 = blockIdx.y*AT_RPC;
    if (tid < AT_RPC*Hh) se[tid] = make_float2(g_eq1[i0*Hh + tid], g_eq2[i0*Hh + tid]);
    __syncthreads();
    float rz[2][Hh];
    #pragma unroll
    for (int l = 0; l < 2; l++)
        #pragma unroll
        for (int h = 0; h < Hh; h += 4)
            *(float4*)&rz[l][h] = *(const float4*)&g_rZ[(size_t)(j+l)*Hh + h];
    float cb = pwb[0]*pwbc[0], wg = pwg[0];
    #pragma unroll
    for (int ii = 0; ii < AT_RPC; ii++) {
        size_t idx = (size_t)(i0+ii)*Nn + j;
        float2 dg = *(const float2*)&deg[idx];
        float2 bd = *(const float2*)&bond[idx];
        float2 ds = *(const float2*)&dist[idx];
        const float* dgp = &dg.x; const float* bdp = &bd.x; const float* dsp = &ds.x;
        float p[2] = {0.f, 0.f};
        float E1[2], E2[2];
        #pragma unroll
        for (int l = 0; l < 2; l++) {
            float e = fmaf(bdp[l], cb, dsp[l]*wg);
            float f = dgp[l] > 0.f ? 1.f : 0.f;
            float e2 = __expf(0.2f*e) * f;
            float e2sq = e2*e2;
            E2[l] = e2;
            E1[l] = e2sq*e2sq*e2;
        }
        #pragma unroll
        for (int h = 0; h < Hh; h++) {
            float2 s12 = se[ii*Hh + h];
            #pragma unroll
            for (int l = 0; l < 2; l++)
                p[l] = fmaf(fmaxf(s12.x*E1[l], s12.y*E2[l]), rz[l][h], p[l]);
        }
        __nv_bfloat16 hi2[2], lo2[2];
        #pragma unroll
        for (int l = 0; l < 2; l++) {
            float pv = p[l] * 0.125f;
            hi2[l] = __float2bfloat16(pv);
            lo2[l] = __float2bfloat16(pv - __bfloat162float(hi2[l]));
        }
        *(uint32_t*)&g_Phi[idx] = *(uint32_t*)hi2;
        *(uint32_t*)&g_Plo[idx] = *(uint32_t*)lo2;
    }
}

// ---------------- HMMA GEMM: U = elu(P @ v), 64x64 tiles, full-K ----------------
#define PV_TILE  (64*80)     // 5120 B
#define PV_AHI   0
#define PV_ALO   (PV_TILE)
#define PV_BHI   (2*PV_TILE)
#define PV_BLO   (3*PV_TILE)
#define PV_STAGE (4*PV_TILE) // 20480

__global__ void __launch_bounds__(256) gemm_pv_mma(float* __restrict__ outU) {
    __shared__ __align__(16) char smem[2*PV_STAGE];
    uint32_t sb = smem_u32(smem);
    const int tid = threadIdx.x, lane = tid & 31, wid = tid >> 5;
    const int mbase = (wid & 3)*16, nbase = (wid >> 2)*32;
    const int bi = blockIdx.y*64, bc = blockIdx.x*64;
    const int row = tid >> 2, ch = tid & 3;
    const int NT = Nn/BK;                     // 64

    float acc[4][4] = {};
    uint4 pa0, pa1, pb0, pb1;
    {
        int k0 = ch*8;
        pa0 = *(const uint4*)&g_Phi[(size_t)(bi + row)*Nn + k0];
        pa1 = *(const uint4*)&g_Plo[(size_t)(bi + row)*Nn + k0];
        pb0 = *(const uint4*)&g_vThi[(size_t)(bc + row)*Nn + k0];
        pb1 = *(const uint4*)&g_vTlo[(size_t)(bc + row)*Nn + k0];
        *(uint4*)(smem + PV_AHI + row*80 + ch*16) = pa0;
        *(uint4*)(smem + PV_ALO + row*80 + ch*16) = pa1;
        *(uint4*)(smem + PV_BHI + row*80 + ch*16) = pb0;
        *(uint4*)(smem + PV_BLO + row*80 + ch*16) = pb1;
    }
    __syncthreads();

    for (int kt = 0; kt < NT; kt++) {
        int cur = kt & 1, nxt = cur ^ 1;
        if (kt + 1 < NT) {
            int k0 = (kt+1)*BK + ch*8;
            pa0 = *(const uint4*)&g_Phi[(size_t)(bi + row)*Nn + k0];
            pa1 = *(const uint4*)&g_Plo[(size_t)(bi + row)*Nn + k0];
            pb0 = *(const uint4*)&g_vThi[(size_t)(bc + row)*Nn + k0];
            pb1 = *(const uint4*)&g_vTlo[(size_t)(bc + row)*Nn + k0];
        }
        uint32_t base = sb + cur*PV_STAGE;
        #pragma unroll
        for (int kk = 0; kk < 2; kk++) {
            uint32_t rsel = lane & 15;
            uint32_t csel = (kk*16 + ((lane >> 4) << 3)) * 2;
            uint32_t ah[4], al[4], bh[2][4], bl[2][4];
            ldm4(ah, base + PV_AHI + (mbase + rsel)*80 + csel);
            ldm4(al, base + PV_ALO + (mbase + rsel)*80 + csel);
            #pragma unroll
            for (int ck = 0; ck < 2; ck++) {
                uint32_t ro = (nbase + ck*16 + rsel)*80 + csel;
                ldm4(bh[ck], base + PV_BHI + ro);
                ldm4(bl[ck], base + PV_BLO + ro);
            }
            #pragma unroll
            for (int nt = 0; nt < 4; nt++) {
                int ck = nt >> 1, pr = nt & 1;
                mma16816(acc[nt], ah, bh[ck][pr], bh[ck][2+pr]);
                mma16816(acc[nt], ah, bl[ck][pr], bl[ck][2+pr]);
                mma16816(acc[nt], al, bh[ck][pr], bh[ck][2+pr]);
            }
        }
        if (kt + 1 < NT) {
            *(uint4*)(smem + nxt*PV_STAGE + PV_AHI + row*80 + ch*16) = pa0;
            *(uint4*)(smem + nxt*PV_STAGE + PV_ALO + row*80 + ch*16) = pa1;
            *(uint4*)(smem + nxt*PV_STAGE + PV_BHI + row*80 + ch*16) = pb0;
            *(uint4*)(smem + nxt*PV_STAGE + PV_BLO + row*80 + ch*16) = pb1;
        }
        __syncthreads();
    }

    #pragma unroll
    for (int nt = 0; nt < 4; nt++) {
        int c0 = bc + nbase + nt*8 + (lane & 3)*2;
        #pragma unroll
        for (int half = 0; half < 2; half++) {
            int rr = bi + mbase + (lane >> 2) + half*8;
            float v0 = acc[nt][half*2], v1 = acc[nt][half*2 + 1];
            float e0 = v0 > 0.f ? v0 : expm1f(v0);
            float e1 = v1 > 0.f ? v1 : expm1f(v1);
            *(float2*)&outU[(size_t)rr*Fd + c0] = make_float2(e0, e1);
            __nv_bfloat16 h0 = __float2bfloat16(e0), h1 = __float2bfloat16(e1);
            __nv_bfloat16 l0 = __float2bfloat16(e0 - __bfloat162float(h0));
            __nv_bfloat16 l1 = __float2bfloat16(e1 - __bfloat162float(h1));
            __nv_bfloat162 hv; hv.x = h0; hv.y = h1;
            __nv_bfloat162 lv; lv.x = l0; lv.y = l1;
            *(__nv_bfloat162*)&g_Uhi[(size_t)rr*Fd + c0] = hv;
            *(__nv_bfloat162*)&g_Ulo[(size_t)rr*Fd + c0] = lv;
        }
    }
}

// ---------------- HMMA GEMM: sim = U U^T, 64x64 tiles (528 CTAs), fused epilogue ----------------
#define SM_TILE  (64*80)
#define SM_AHI   0
#define SM_ALO   (SM_TILE)
#define SM_BHI   (2*SM_TILE)
#define SM_BLO   (3*SM_TILE)
#define SM_STAGE (4*SM_TILE)  // 20480

__global__ void __launch_bounds__(256) sim_mma(const float* __restrict__ dist,
                                               const float* __restrict__ deg) {
    int t = blockIdx.x;
    int a = 0;
    while (t >= 32 - a) { t -= 32 - a; a++; }
    int b = a + t;                        // a <= b over 32x32 64-blocks
    int bi = a*64, bj = b*64;

    __shared__ __align__(16) char smem[2*SM_STAGE];
    uint32_t sb = smem_u32(smem);
    const int tid = threadIdx.x, lane = tid & 31, wid = tid >> 5;
    const int mbase = (wid & 3)*16, nbase = (wid >> 2)*32;
    const int row = tid >> 2, ch = tid & 3;
    const int NT = Fd/BK;                 // 8

    float acc[4][4] = {};
    uint4 pa0, pa1, pb0, pb1;
    {
        int k0 = ch*8;
        pa0 = *(const uint4*)&g_Uhi[(size_t)(bi + row)*Fd + k0];
        pa1 = *(const uint4*)&g_Ulo[(size_t)(bi + row)*Fd + k0];
        pb0 = *(const uint4*)&g_Uhi[(size_t)(bj + row)*Fd + k0];
        pb1 = *(const uint4*)&g_Ulo[(size_t)(bj + row)*Fd + k0];
        *(uint4*)(smem + SM_AHI + row*80 + ch*16) = pa0;
        *(uint4*)(smem + SM_ALO + row*80 + ch*16) = pa1;
        *(uint4*)(smem + SM_BHI + row*80 + ch*16) = pb0;
        *(uint4*)(smem + SM_BLO + row*80 + ch*16) = pb1;
    }
    __syncthreads();

    for (int kt = 0; kt < NT; kt++) {
        int cur = kt & 1, nxt = cur ^ 1;
        if (kt + 1 < NT) {
            int k0 = (kt+1)*BK + ch*8;
            pa0 = *(const uint4*)&g_Uhi[(size_t)(bi + row)*Fd + k0];
            pa1 = *(const uint4*)&g_Ulo[(size_t)(bi + row)*Fd + k0];
            pb0 = *(const uint4*)&g_Uhi[(size_t)(bj + row)*Fd + k0];
            pb1 = *(const uint4*)&g_Ulo[(size_t)(bj + row)*Fd + k0];
        }
        uint32_t base = sb + cur*SM_STAGE;
        #pragma unroll
        for (int kk = 0; kk < 2; kk++) {
            uint32_t rsel = lane & 15;
            uint32_t csel = (kk*16 + ((lane >> 4) << 3)) * 2;
            uint32_t ah[4], al[4], bh[2][4], bl[2][4];
            ldm4(ah, base + SM_AHI + (mbase + rsel)*80 + csel);
            ldm4(al, base + SM_ALO + (mbase + rsel)*80 + csel);
            #pragma unroll
            for (int ck = 0; ck < 2; ck++) {
                uint32_t ro = (nbase + ck*16 + rsel)*80 + csel;
                ldm4(bh[ck], base + SM_BHI + ro);
                ldm4(bl[ck], base + SM_BLO + ro);
            }
            #pragma unroll
            for (int nt = 0; nt < 4; nt++) {
                int ck = nt >> 1, pr = nt & 1;
                mma16816(acc[nt], ah, bh[ck][pr], bh[ck][2+pr]);
                mma16816(acc[nt], ah, bl[ck][pr], bl[ck][2+pr]);
                mma16816(acc[nt], al, bh[ck][pr], bh[ck][2+pr]);
            }
        }
        if (kt + 1 < NT) {
            *(uint4*)(smem + nxt*SM_STAGE + SM_AHI + row*80 + ch*16) = pa0;
            *(uint4*)(smem + nxt*SM_STAGE + SM_ALO + row*80 + ch*16) = pa1;
            *(uint4*)(smem + nxt*SM_STAGE + SM_BHI + row*80 + ch*16) = pb0;
            *(uint4*)(smem + nxt*SM_STAGE + SM_BLO + row*80 + ch*16) = pb1;
        }
        __syncthreads();
    }

    // stage sigmoid(sim) into smem [64][65] floats
    float* st = (float*)smem;
    #pragma unroll
    for (int nt = 0; nt < 4; nt++) {
        int c0 = nbase + nt*8 + (lane & 3)*2;
        int r0 = mbase + (lane >> 2);
        st[r0*65 + c0]       = 1.f / (1.f + __expf(-acc[nt][0]));
        st[r0*65 + c0 + 1]   = 1.f / (1.f + __expf(-acc[nt][1]));
        st[(r0+8)*65 + c0]   = 1.f / (1.f + __expf(-acc[nt][2]));
        st[(r0+8)*65 + c0+1] = 1.f / (1.f + __expf(-acc[nt][3]));
    }
    __syncthreads();
    // direct block C[bi+row, bj+col]; LN partials for col-block b, rows bi..
    #pragma unroll
    for (int rep = 0; rep < 2; rep++) {
        int lin = rep*256 + tid;
        int rr = lin >> 3;
        int cb = (lin & 7) << 3;
        size_t idx = (size_t)(bi + rr)*Nn + bj + cb;
        float4 d0 = *(const float4*)&dist[idx];
        float4 d1 = *(const float4*)&dist[idx + 4];
        float4 m0 = *(const float4*)&deg[idx];
        float4 m1 = *(const float4*)&deg[idx + 4];
        const float* sr = &st[rr*65 + cb];
        float4 o0 = make_float4(sr[0]*(-d0.x)*m0.x, sr[1]*(-d0.y)*m0.y,
                                sr[2]*(-d0.z)*m0.z, sr[3]*(-d0.w)*m0.w);
        float4 o1 = make_float4(sr[4]*(-d1.x)*m1.x, sr[5]*(-d1.y)*m1.y,
                                sr[6]*(-d1.z)*m1.z, sr[7]*(-d1.w)*m1.w);
        *(float4*)&g_C[idx]     = o0;
        *(float4*)&g_C[idx + 4] = o1;
        float s  = ((o0.x+o0.y)+(o0.z+o0.w)) + ((o1.x+o1.y)+(o1.z+o1.w));
        float s2 = fmaf(o0.x,o0.x, fmaf(o0.y,o0.y, fmaf(o0.z,o0.z, fmaf(o0.w,o0.w,
                   fmaf(o1.x,o1.x, fmaf(o1.y,o1.y, fmaf(o1.z,o1.z, o1.w*o1.w)))))));
        #pragma unroll
        for (int off = 4; off > 0; off >>= 1) {
            s  += __shfl_down_sync(0xffffffffu, s,  off, 8);
            s2 += __shfl_down_sync(0xffffffffu, s2, off, 8);
        }
        if ((tid & 7) == 0) {
            g_Sp[(size_t)b*Nn + bi + rr]  = s;
            g_S2p[(size_t)b*Nn + bi + rr] = s2;
        }
    }
    // mirror block C[bj+row, bi+col]; LN partials for col-block a, rows bj..
    if (a != b) {
        #pragma unroll
        for (int rep = 0; rep < 2; rep++) {
            int lin = rep*256 + tid;
            int rr = lin >> 3;
            int cb = (lin & 7) << 3;
            size_t idx = (size_t)(bj + rr)*Nn + bi + cb;
            float4 d0 = *(const float4*)&dist[idx];
            float4 d1 = *(const float4*)&dist[idx + 4];
            float4 m0 = *(const float4*)&deg[idx];
            float4 m1 = *(const float4*)&deg[idx + 4];
            float sv[8];
            #pragma unroll
            for (int k = 0; k < 8; k++) sv[k] = st[(cb + k)*65 + rr];
            float4 o0 = make_float4(sv[0]*(-d0.x)*m0.x, sv[1]*(-d0.y)*m0.y,
                                    sv[2]*(-d0.z)*m0.z, sv[3]*(-d0.w)*m0.w);
            float4 o1 = make_float4(sv[4]*(-d1.x)*m1.x, sv[5]*(-d1.y)*m1.y,
                                    sv[6]*(-d1.z)*m1.z, sv[7]*(-d1.w)*m1.w);
            *(float4*)&g_C[idx]     = o0;
            *(float4*)&g_C[idx + 4] = o1;
            float s  = ((o0.x+o0.y)+(o0.z+o0.w)) + ((o1.x+o1.y)+(o1.z+o1.w));
            float s2 = fmaf(o0.x,o0.x, fmaf(o0.y,o0.y, fmaf(o0.z,o0.z, fmaf(o0.w,o0.w,
                       fmaf(o1.x,o1.x, fmaf(o1.y,o1.y, fmaf(o1.z,o1.z, o1.w*o1.w)))))));
            #pragma unroll
            for (int off = 4; off > 0; off >>= 1) {
                s  += __shfl_down_sync(0xffffffffu, s,  off, 8);
                s2 += __shfl_down_sync(0xffffffffu, s2, off, 8);
            }
            if ((tid & 7) == 0) {
                g_Sp[(size_t)a*Nn + bj + rr]  = s;
                g_S2p[(size_t)a*Nn + bj + rr] = s2;
            }
        }
    }
}

// ---------------- finish LN stats from partials ----------------
__global__ void rn_stats2_kernel() {
    int i = blockIdx.x*256 + threadIdx.x;   // < Nn
    float s = 0.f, s2 = 0.f;
    #pragma unroll
    for (int c = 0; c < 32; c++) {
        s  += g_Sp[(size_t)c*Nn + i];
        s2 += g_S2p[(size_t)c*Nn + i];
    }
    float mean = s * (1.f/Nn);
    float var  = s2 * (1.f/Nn) - mean*mean;
    g_mu[i] = mean;
    g_rs[i] = rsqrtf(var + 1e-5f);
}

// ---------------- out = norm(C) + norm(C)^T  (symmetric: compute once, write twice) ----------------
__global__ void symadd_kernel(float* __restrict__ outC) {
    int t = blockIdx.x;
    int a = 0;
    while (t >= 64 - a) { t -= 64 - a; a++; }
    int b = a + t;   // a <= b, 32x32 blocks
    __shared__ float tA[32][33], tB[32][33], tV[32][33];
    int tx = threadIdx.x, ty = threadIdx.y;
    #pragma unroll
    for (int r = 0; r < 32; r += 8) {
        tA[ty + r][tx] = g_C[(size_t)(a*32 + ty + r)*Nn + b*32 + tx];
        tB[ty + r][tx] = g_C[(size_t)(b*32 + ty + r)*Nn + a*32 + tx];
    }
    int j = b*32 + tx;
    float muj = g_mu[j], rsj = g_rs[j];
    __syncthreads();
    #pragma unroll
    for (int r = 0; r < 32; r += 8) {
        int i = a*32 + ty + r;
        float v = (tA[ty + r][tx] - g_mu[i])*g_rs[i] + (tB[tx][ty + r] - muj)*rsj;
        outC[(size_t)i*Nn + j] = v;
        tV[ty + r][tx] = v;
    }
    if (a != b) {
        __syncthreads();
        #pragma unroll
        for (int r = 0; r < 32; r += 8)
            outC[(size_t)(b*32 + ty + r)*Nn + a*32 + tx] = tV[tx][ty + r];
    }
}

extern "C" void kernel_launch(void* const* d_in, const int* in_sizes, int n_in,
                              void* d_out, int out_size) {
    const float* X    = (const float*)d_in[0];
    const float* dist = (const float*)d_in[1];
    const float* bond = (const float*)d_in[2];
    const float* deg  = (const float*)d_in[4];
    const float* Wq   = (const float*)d_in[5];
    const float* Wk   = (const float*)d_in[6];
    const float* Wv   = (const float*)d_in[7];
    const float* wb   = (const float*)d_in[8];
    const float* wbc  = (const float*)d_in[9];
    const float* wg   = (const float*)d_in[10];
    float* out  = (float*)d_out;
    float* outU = out;
    float* outC = out + Nn*Fd;

    // side stream (capture-safe fork/join): gemm_v runs concurrently with the
    // attention chain; it is only needed by gemm_pv_mma.
    cudaStream_t s2;
    cudaStreamCreateWithFlags(&s2, cudaStreamNonBlocking);
    cudaEvent_t evFork, evJoin;
    cudaEventCreateWithFlags(&evFork, cudaEventDisableTiming);
    cudaEventCreateWithFlags(&evJoin, cudaEventDisableTiming);

    qk_kernel<<<Nn, 256>>>(X, Wq, Wk);
    cudaEventRecord(evFork, 0);
    cudaStreamWaitEvent(s2, evFork, 0);
    gemm_v_kernel<<<dim3(Fd/64, Nn/64), 256, 0, s2>>>(X, Wv);
    cudaEventRecord(evJoin, s2);

    colz_kernel<<<dim3(16, ICP), 128>>>(bond, dist, deg, wb, wbc, wg);
    zred1_kernel<<<dim3(NH/256, 16), 256>>>();
    zred2_kernel<<<NH/256, 256>>>();
    attnp_kernel<<<dim3(4, 256), 256>>>(bond, dist, deg, wb, wbc, wg);
    cudaStreamWaitEvent(0, evJoin, 0);
    gemm_pv_mma<<<dim3(Fd/64, Nn/64), 256>>>(outU);
    sim_mma<<<32*33/2, 256>>>(dist, deg);
    rn_stats2_kernel<<<Nn/256, 256>>>();
    symadd_kernel<<<64*65/2, dim3(32, 8)>>>(outC);

    cudaEventDestroy(evFork);
    cudaEventDestroy(evJoin);
    cudaStreamDestroy(s2);
}

// round 17
// speedup vs baseline: 1.0779x; 1.0109x over previous
#include <cuda_runtime.h>
#include <cuda_bf16.h>
#include <math.h>
#include <stdint.h>

#define Nn 2048
#define Fd 256
#define Hh 8
#define NH (Nn*Hh)
#define ICP 64           // i-chunks for Z partials (colz: 32 rows per chunk)
#define CZ_RPC 32
#define AT_RPC 8         // attnp rows per chunk (grid y = 256)
#define BK 32

// ---------------- scratch (static device globals) ----------------
__device__ float g_eq1[NH];
__device__ float g_eq2[NH];
__device__ float g_rZ[NH];
__device__ float g_P[ICP*NH];                          // Z-partials (4MB)
__device__ float g_Zs[16*NH];                          // zred stage-1 partials (2MB)
__device__ __align__(16) __nv_bfloat16 g_Phi[Nn*Nn];   // P hi [N][N]
__device__ __align__(16) __nv_bfloat16 g_Plo[Nn*Nn];   // P lo
__device__ __align__(16) __nv_bfloat16 g_vThi[Fd*Nn];  // v^T hi [F][N]
__device__ __align__(16) __nv_bfloat16 g_vTlo[Fd*Nn];
__device__ __align__(16) __nv_bfloat16 g_Uhi[Nn*Fd];   // U hi [N][F]
__device__ __align__(16) __nv_bfloat16 g_Ulo[Nn*Fd];
__device__ float g_C[Nn*Nn];
__device__ float g_Sp[32*Nn];                          // LN row-sum partials per 64-col block
__device__ float g_S2p[32*Nn];
__device__ float g_mu[Nn];
__device__ float g_rs[Nn];

// ---------------- mma helpers ----------------
__device__ __forceinline__ uint32_t smem_u32(const void* p) {
    uint32_t a;
    asm("{ .reg .u64 t; cvta.to.shared.u64 t, %1; cvt.u32.u64 %0, t; }" : "=r"(a) : "l"(p));
    return a;
}
__device__ __forceinline__ void ldm4(uint32_t* r, uint32_t addr) {
    asm volatile("ldmatrix.sync.aligned.m8n8.x4.shared.b16 {%0,%1,%2,%3}, [%4];"
        : "=r"(r[0]), "=r"(r[1]), "=r"(r[2]), "=r"(r[3]) : "r"(addr));
}
__device__ __forceinline__ void mma16816(float* c, const uint32_t* a, uint32_t b0, uint32_t b1) {
    asm volatile("mma.sync.aligned.m16n8k16.row.col.f32.bf16.bf16.f32 "
        "{%0,%1,%2,%3}, {%4,%5,%6,%7}, {%8,%9}, {%0,%1,%2,%3};"
        : "+f"(c[0]), "+f"(c[1]), "+f"(c[2]), "+f"(c[3])
        : "r"(a[0]), "r"(a[1]), "r"(a[2]), "r"(a[3]), "r"(b0), "r"(b1));
}

// ---------------- qk projection ----------------
__global__ void qk_kernel(const float* __restrict__ X, const float* __restrict__ Wq,
                          const float* __restrict__ Wk) {
    __shared__ float xs[Fd];
    int i = blockIdx.x;
    int t = threadIdx.x;
    xs[t] = X[i*Fd + t];
    __syncthreads();
    int w = t >> 5, lane = t & 31;
    float qa = 0.f, ka = 0.f;
    #pragma unroll
    for (int c = lane; c < Fd; c += 32) {
        float x = xs[c];
        qa = fmaf(x, Wq[c*Hh + w], qa);
        ka = fmaf(x, Wk[c*Hh + w], ka);
    }
    #pragma unroll
    for (int o = 16; o > 0; o >>= 1) {
        qa += __shfl_down_sync(0xffffffffu, qa, o);
        ka += __shfl_down_sync(0xffffffffu, ka, o);
    }
    if (lane == 0) {
        float qk = (qa + ka) * (0.0625f * 0.3535533905932738f);
        g_eq1[i*Hh + w] = __expf(qk);
        g_eq2[i*Hh + w] = __expf(0.2f * qk);
    }
}

// ---------------- v = X @ Wv / 16, fused transpose + hi/lo split ----------------
__global__ void gemm_v_kernel(const float* __restrict__ X, const float* __restrict__ Wv) {
    __shared__ float As[16][64];
    __shared__ float Bs[16][64];
    __shared__ float vs[64][65];
    int tid = threadIdx.x;
    int bi = blockIdx.y * 64;
    int bc = blockIdx.x * 64;
    int arow = tid >> 2,  acol = (tid & 3)  << 2;
    int brow = tid >> 4,  bcol = (tid & 15) << 2;
    int ty   = tid >> 4,  tx   = tid & 15;
    float acc[4][4] = {};
    for (int k0 = 0; k0 < Fd; k0 += 16) {
        float4 a = *(const float4*)&X[(size_t)(bi + arow)*Fd + k0 + acol];
        float4 b = *(const float4*)&Wv[(size_t)(k0 + brow)*Fd + bc + bcol];
        As[acol+0][arow] = a.x; As[acol+1][arow] = a.y;
        As[acol+2][arow] = a.z; As[acol+3][arow] = a.w;
        *(float4*)&Bs[brow][bcol] = b;
        __syncthreads();
        #pragma unroll
        for (int kk = 0; kk < 16; kk++) {
            float ar[4], br[4];
            *(float4*)ar = *(const float4*)&As[kk][ty*4];
            *(float4*)br = *(const float4*)&Bs[kk][tx*4];
            #pragma unroll
            for (int r = 0; r < 4; r++)
                #pragma unroll
                for (int c = 0; c < 4; c++)
                    acc[r][c] = fmaf(ar[r], br[c], acc[r][c]);
        }
        __syncthreads();
    }
    #pragma unroll
    for (int r = 0; r < 4; r++)
        #pragma unroll
        for (int c = 0; c < 4; c++)
            vs[ty*4 + r][tx*4 + c] = acc[r][c] * 0.0625f;
    __syncthreads();
    #pragma unroll
    for (int r = 0; r < 4; r++) {
        int wf = ty*4 + r;
        __nv_bfloat16 hi4[4], lo4[4];
        #pragma unroll
        for (int c = 0; c < 4; c++) {
            float x = vs[tx*4 + c][wf];
            hi4[c] = __float2bfloat16(x);
            lo4[c] = __float2bfloat16(x - __bfloat162float(hi4[c]));
        }
        size_t off = (size_t)(bc + wf)*Nn + bi + tx*4;
        *(uint2*)&g_vThi[off] = *(uint2*)hi4;
        *(uint2*)&g_vTlo[off] = *(uint2*)lo4;
    }
}

// ---------------- pass B: column softmax denominators (j-half via jbase) ----------------
__global__ void colz_kernel(const float* __restrict__ bond, const float* __restrict__ dist,
                            const float* __restrict__ deg, const float* __restrict__ pwb,
                            const float* __restrict__ pwbc, const float* __restrict__ pwg,
                            int jbase) {
    __shared__ float2 se[CZ_RPC*Hh];
    int tid = threadIdx.x;
    int j = jbase + blockIdx.x*128 + tid;
    int i0 = blockIdx.y*CZ_RPC;
    for (int t = tid; t < CZ_RPC*Hh; t += 128)
        se[t] = make_float2(g_eq1[i0*Hh + t], g_eq2[i0*Hh + t]);
    __syncthreads();
    float cb = pwb[0]*pwbc[0], wg = pwg[0];
    float z[Hh];
    #pragma unroll
    for (int h = 0; h < Hh; h++) z[h] = 0.f;
    #pragma unroll 4
    for (int ii = 0; ii < CZ_RPC; ii++) {
        size_t idx = (size_t)(i0+ii)*Nn + j;
        float dg = deg[idx], bd = bond[idx], ds = dist[idx];
        float e = fmaf(bd, cb, ds*wg);
        float f = dg > 0.f ? 1.f : 0.f;
        float e2 = __expf(0.2f*e) * f;
        float e2sq = e2*e2;
        float e1 = e2sq*e2sq*e2;   // exp(e)*f
        #pragma unroll
        for (int h = 0; h < Hh; h++) {
            float2 s12 = se[ii*Hh + h];
            z[h] += fmaxf(s12.x*e1, s12.y*e2);
        }
    }
    float* zp = &g_P[(size_t)blockIdx.y*NH + (size_t)j*Hh];
    *(float4*)&zp[0] = make_float4(z[0], z[1], z[2], z[3]);
    *(float4*)&zp[4] = make_float4(z[4], z[5], z[6], z[7]);
}

// ---------------- zred: two-stage deterministic reduction (per t-half) ----------------
__global__ void zred1_kernel(int tbase) {
    int t = tbase + blockIdx.x*256 + threadIdx.x;
    int c0 = blockIdx.y*4;
    float s = (g_P[(size_t)(c0+0)*NH + t] + g_P[(size_t)(c0+1)*NH + t])
            + (g_P[(size_t)(c0+2)*NH + t] + g_P[(size_t)(c0+3)*NH + t]);
    g_Zs[(size_t)blockIdx.y*NH + t] = s;
}
__global__ void zred2_kernel(int tbase) {
    int t = tbase + blockIdx.x*256 + threadIdx.x;
    float s = 0.f;
    #pragma unroll
    for (int c = 0; c < 16; c++) s += g_Zs[(size_t)c*NH + t];
    g_rZ[t] = 1.f / s;
}

// ---------------- pass C: P -> bf16 hi/lo (2 cols/thread; j-half via jbase) ----------------
__global__ void __launch_bounds__(256) attnp_kernel(
        const float* __restrict__ bond, const float* __restrict__ dist,
        const float* __restrict__ deg, const float* __restrict__ pwb,
        const float* __restrict__ pwbc, const float* __restrict__ pwg,
        int jbase) {
    __shared__ float2 se[AT_RPC*Hh];
    int tid = threadIdx.x;
    int j = jbase + blockIdx.x*512 + tid*2;
    int i0 = blockIdx.y*AT_RPC;
    if (tid < AT_RPC*Hh) se[tid] = make_float2(g_eq1[i0*Hh + tid], g_eq2[i0*Hh + tid]);
    __syncthreads();
    float rz[2][Hh];
    #pragma unroll
    for (int l = 0; l < 2; l++)
        #pragma unroll
        for (int h = 0; h < Hh; h += 4)
            *(float4*)&rz[l][h] = *(const float4*)&g_rZ[(size_t)(j+l)*Hh + h];
    float cb = pwb[0]*pwbc[0], wg = pwg[0];
    #pragma unroll
    for (int ii = 0; ii < AT_RPC; ii++) {
        size_t idx = (size_t)(i0+ii)*Nn + j;
        float2 dg = *(const float2*)&deg[idx];
        float2 bd = *(const float2*)&bond[idx];
        float2 ds = *(const float2*)&dist[idx];
        const float* dgp = &dg.x; const float* bdp = &bd.x; const float* dsp = &ds.x;
        float p[2] = {0.f, 0.f};
        float E1[2], E2[2];
        #pragma unroll
        for (int l = 0; l < 2; l++) {
            float e = fmaf(bdp[l], cb, dsp[l]*wg);
            float f = dgp[l] > 0.f ? 1.f : 0.f;
            float e2 = __expf(0.2f*e) * f;
            float e2sq = e2*e2;
            E2[l] = e2;
            E1[l] = e2sq*e2sq*e2;
        }
        #pragma unroll
        for (int h = 0; h < Hh; h++) {
            float2 s12 = se[ii*Hh + h];
            #pragma unroll
            for (int l = 0; l < 2; l++)
                p[l] = fmaf(fmaxf(s12.x*E1[l], s12.y*E2[l]), rz[l][h], p[l]);
        }
        __nv_bfloat16 hi2[2], lo2[2];
        #pragma unroll
        for (int l = 0; l < 2; l++) {
            float pv = p[l] * 0.125f;
            hi2[l] = __float2bfloat16(pv);
            lo2[l] = __float2bfloat16(pv - __bfloat162float(hi2[l]));
        }
        *(uint32_t*)&g_Phi[idx] = *(uint32_t*)hi2;
        *(uint32_t*)&g_Plo[idx] = *(uint32_t*)lo2;
    }
}

// ---------------- HMMA GEMM: U = elu(P @ v), 64x64 tiles, full-K ----------------
#define PV_TILE  (64*80)     // 5120 B
#define PV_AHI   0
#define PV_ALO   (PV_TILE)
#define PV_BHI   (2*PV_TILE)
#define PV_BLO   (3*PV_TILE)
#define PV_STAGE (4*PV_TILE) // 20480

__global__ void __launch_bounds__(256) gemm_pv_mma(float* __restrict__ outU) {
    __shared__ __align__(16) char smem[2*PV_STAGE];
    uint32_t sb = smem_u32(smem);
    const int tid = threadIdx.x, lane = tid & 31, wid = tid >> 5;
    const int mbase = (wid & 3)*16, nbase = (wid >> 2)*32;
    const int bi = blockIdx.y*64, bc = blockIdx.x*64;
    const int row = tid >> 2, ch = tid & 3;
    const int NT = Nn/BK;                     // 64

    float acc[4][4] = {};
    uint4 pa0, pa1, pb0, pb1;
    {
        int k0 = ch*8;
        pa0 = *(const uint4*)&g_Phi[(size_t)(bi + row)*Nn + k0];
        pa1 = *(const uint4*)&g_Plo[(size_t)(bi + row)*Nn + k0];
        pb0 = *(const uint4*)&g_vThi[(size_t)(bc + row)*Nn + k0];
        pb1 = *(const uint4*)&g_vTlo[(size_t)(bc + row)*Nn + k0];
        *(uint4*)(smem + PV_AHI + row*80 + ch*16) = pa0;
        *(uint4*)(smem + PV_ALO + row*80 + ch*16) = pa1;
        *(uint4*)(smem + PV_BHI + row*80 + ch*16) = pb0;
        *(uint4*)(smem + PV_BLO + row*80 + ch*16) = pb1;
    }
    __syncthreads();

    for (int kt = 0; kt < NT; kt++) {
        int cur = kt & 1, nxt = cur ^ 1;
        if (kt + 1 < NT) {
            int k0 = (kt+1)*BK + ch*8;
            pa0 = *(const uint4*)&g_Phi[(size_t)(bi + row)*Nn + k0];
            pa1 = *(const uint4*)&g_Plo[(size_t)(bi + row)*Nn + k0];
            pb0 = *(const uint4*)&g_vThi[(size_t)(bc + row)*Nn + k0];
            pb1 = *(const uint4*)&g_vTlo[(size_t)(bc + row)*Nn + k0];
        }
        uint32_t base = sb + cur*PV_STAGE;
        #pragma unroll
        for (int kk = 0; kk < 2; kk++) {
            uint32_t rsel = lane & 15;
            uint32_t csel = (kk*16 + ((lane >> 4) << 3)) * 2;
            uint32_t ah[4], al[4], bh[2][4], bl[2][4];
            ldm4(ah, base + PV_AHI + (mbase + rsel)*80 + csel);
            ldm4(al, base + PV_ALO + (mbase + rsel)*80 + csel);
            #pragma unroll
            for (int ck = 0; ck < 2; ck++) {
                uint32_t ro = (nbase + ck*16 + rsel)*80 + csel;
                ldm4(bh[ck], base + PV_BHI + ro);
                ldm4(bl[ck], base + PV_BLO + ro);
            }
            #pragma unroll
            for (int nt = 0; nt < 4; nt++) {
                int ck = nt >> 1, pr = nt & 1;
                mma16816(acc[nt], ah, bh[ck][pr], bh[ck][2+pr]);
                mma16816(acc[nt], ah, bl[ck][pr], bl[ck][2+pr]);
                mma16816(acc[nt], al, bh[ck][pr], bh[ck][2+pr]);
            }
        }
        if (kt + 1 < NT) {
            *(uint4*)(smem + nxt*PV_STAGE + PV_AHI + row*80 + ch*16) = pa0;
            *(uint4*)(smem + nxt*PV_STAGE + PV_ALO + row*80 + ch*16) = pa1;
            *(uint4*)(smem + nxt*PV_STAGE + PV_BHI + row*80 + ch*16) = pb0;
            *(uint4*)(smem + nxt*PV_STAGE + PV_BLO + row*80 + ch*16) = pb1;
        }
        __syncthreads();
    }

    #pragma unroll
    for (int nt = 0; nt < 4; nt++) {
        int c0 = bc + nbase + nt*8 + (lane & 3)*2;
        #pragma unroll
        for (int half = 0; half < 2; half++) {
            int rr = bi + mbase + (lane >> 2) + half*8;
            float v0 = acc[nt][half*2], v1 = acc[nt][half*2 + 1];
            float e0 = v0 > 0.f ? v0 : expm1f(v0);
            float e1 = v1 > 0.f ? v1 : expm1f(v1);
            *(float2*)&outU[(size_t)rr*Fd + c0] = make_float2(e0, e1);
            __nv_bfloat16 h0 = __float2bfloat16(e0), h1 = __float2bfloat16(e1);
            __nv_bfloat16 l0 = __float2bfloat16(e0 - __bfloat162float(h0));
            __nv_bfloat16 l1 = __float2bfloat16(e1 - __bfloat162float(h1));
            __nv_bfloat162 hv; hv.x = h0; hv.y = h1;
            __nv_bfloat162 lv; lv.x = l0; lv.y = l1;
            *(__nv_bfloat162*)&g_Uhi[(size_t)rr*Fd + c0] = hv;
            *(__nv_bfloat162*)&g_Ulo[(size_t)rr*Fd + c0] = lv;
        }
    }
}

// ---------------- HMMA GEMM: sim = U U^T, 64x64 tiles (528 CTAs), fused epilogue ----------------
#define SM_TILE  (64*80)
#define SM_AHI   0
#define SM_ALO   (SM_TILE)
#define SM_BHI   (2*SM_TILE)
#define SM_BLO   (3*SM_TILE)
#define SM_STAGE (4*SM_TILE)  // 20480

__global__ void __launch_bounds__(256) sim_mma(const float* __restrict__ dist,
                                               const float* __restrict__ deg) {
    int t = blockIdx.x;
    int a = 0;
    while (t >= 32 - a) { t -= 32 - a; a++; }
    int b = a + t;                        // a <= b over 32x32 64-blocks
    int bi = a*64, bj = b*64;

    __shared__ __align__(16) char smem[2*SM_STAGE];
    uint32_t sb = smem_u32(smem);
    const int tid = threadIdx.x, lane = tid & 31, wid = tid >> 5;
    const int mbase = (wid & 3)*16, nbase = (wid >> 2)*32;
    const int row = tid >> 2, ch = tid & 3;
    const int NT = Fd/BK;                 // 8

    float acc[4][4] = {};
    uint4 pa0, pa1, pb0, pb1;
    {
        int k0 = ch*8;
        pa0 = *(const uint4*)&g_Uhi[(size_t)(bi + row)*Fd + k0];
        pa1 = *(const uint4*)&g_Ulo[(size_t)(bi + row)*Fd + k0];
        pb0 = *(const uint4*)&g_Uhi[(size_t)(bj + row)*Fd + k0];
        pb1 = *(const uint4*)&g_Ulo[(size_t)(bj + row)*Fd + k0];
        *(uint4*)(smem + SM_AHI + row*80 + ch*16) = pa0;
        *(uint4*)(smem + SM_ALO + row*80 + ch*16) = pa1;
        *(uint4*)(smem + SM_BHI + row*80 + ch*16) = pb0;
        *(uint4*)(smem + SM_BLO + row*80 + ch*16) = pb1;
    }
    __syncthreads();

    for (int kt = 0; kt < NT; kt++) {
        int cur = kt & 1, nxt = cur ^ 1;
        if (kt + 1 < NT) {
            int k0 = (kt+1)*BK + ch*8;
            pa0 = *(const uint4*)&g_Uhi[(size_t)(bi + row)*Fd + k0];
            pa1 = *(const uint4*)&g_Ulo[(size_t)(bi + row)*Fd + k0];
            pb0 = *(const uint4*)&g_Uhi[(size_t)(bj + row)*Fd + k0];
            pb1 = *(const uint4*)&g_Ulo[(size_t)(bj + row)*Fd + k0];
        }
        uint32_t base = sb + cur*SM_STAGE;
        #pragma unroll
        for (int kk = 0; kk < 2; kk++) {
            uint32_t rsel = lane & 15;
            uint32_t csel = (kk*16 + ((lane >> 4) << 3)) * 2;
            uint32_t ah[4], al[4], bh[2][4], bl[2][4];
            ldm4(ah, base + SM_AHI + (mbase + rsel)*80 + csel);
            ldm4(al, base + SM_ALO + (mbase + rsel)*80 + csel);
            #pragma unroll
            for (int ck = 0; ck < 2; ck++) {
                uint32_t ro = (nbase + ck*16 + rsel)*80 + csel;
                ldm4(bh[ck], base + SM_BHI + ro);
                ldm4(bl[ck], base + SM_BLO + ro);
            }
            #pragma unroll
            for (int nt = 0; nt < 4; nt++) {
                int ck = nt >> 1, pr = nt & 1;
                mma16816(acc[nt], ah, bh[ck][pr], bh[ck][2+pr]);
                mma16816(acc[nt], ah, bl[ck][pr], bl[ck][2+pr]);
                mma16816(acc[nt], al, bh[ck][pr], bh[ck][2+pr]);
            }
        }
        if (kt + 1 < NT) {
            *(uint4*)(smem + nxt*SM_STAGE + SM_AHI + row*80 + ch*16) = pa0;
            *(uint4*)(smem + nxt*SM_STAGE + SM_ALO + row*80 + ch*16) = pa1;
            *(uint4*)(smem + nxt*SM_STAGE + SM_BHI + row*80 + ch*16) = pb0;
            *(uint4*)(smem + nxt*SM_STAGE + SM_BLO + row*80 + ch*16) = pb1;
        }
        __syncthreads();
    }

    // stage sigmoid(sim) into smem [64][65] floats
    float* st = (float*)smem;
    #pragma unroll
    for (int nt = 0; nt < 4; nt++) {
        int c0 = nbase + nt*8 + (lane & 3)*2;
        int r0 = mbase + (lane >> 2);
        st[r0*65 + c0]       = 1.f / (1.f + __expf(-acc[nt][0]));
        st[r0*65 + c0 + 1]   = 1.f / (1.f + __expf(-acc[nt][1]));
        st[(r0+8)*65 + c0]   = 1.f / (1.f + __expf(-acc[nt][2]));
        st[(r0+8)*65 + c0+1] = 1.f / (1.f + __expf(-acc[nt][3]));
    }
    __syncthreads();
    // direct block C[bi+row, bj+col]; LN partials for col-block b, rows bi..
    #pragma unroll
    for (int rep = 0; rep < 2; rep++) {
        int lin = rep*256 + tid;
        int rr = lin >> 3;
        int cb = (lin & 7) << 3;
        size_t idx = (size_t)(bi + rr)*Nn + bj + cb;
        float4 d0 = *(const float4*)&dist[idx];
        float4 d1 = *(const float4*)&dist[idx + 4];
        float4 m0 = *(const float4*)&deg[idx];
        float4 m1 = *(const float4*)&deg[idx + 4];
        const float* sr = &st[rr*65 + cb];
        float4 o0 = make_float4(sr[0]*(-d0.x)*m0.x, sr[1]*(-d0.y)*m0.y,
                                sr[2]*(-d0.z)*m0.z, sr[3]*(-d0.w)*m0.w);
        float4 o1 = make_float4(sr[4]*(-d1.x)*m1.x, sr[5]*(-d1.y)*m1.y,
                                sr[6]*(-d1.z)*m1.z, sr[7]*(-d1.w)*m1.w);
        *(float4*)&g_C[idx]     = o0;
        *(float4*)&g_C[idx + 4] = o1;
        float s  = ((o0.x+o0.y)+(o0.z+o0.w)) + ((o1.x+o1.y)+(o1.z+o1.w));
        float s2 = fmaf(o0.x,o0.x, fmaf(o0.y,o0.y, fmaf(o0.z,o0.z, fmaf(o0.w,o0.w,
                   fmaf(o1.x,o1.x, fmaf(o1.y,o1.y, fmaf(o1.z,o1.z, o1.w*o1.w)))))));
        #pragma unroll
        for (int off = 4; off > 0; off >>= 1) {
            s  += __shfl_down_sync(0xffffffffu, s,  off, 8);
            s2 += __shfl_down_sync(0xffffffffu, s2, off, 8);
        }
        if ((tid & 7) == 0) {
            g_Sp[(size_t)b*Nn + bi + rr]  = s;
            g_S2p[(size_t)b*Nn + bi + rr] = s2;
        }
    }
    // mirror block C[bj+row, bi+col]; LN partials for col-block a, rows bj..
    if (a != b) {
        #pragma unroll
        for (int rep = 0; rep < 2; rep++) {
            int lin = rep*256 + tid;
            int rr = lin >> 3;
            int cb = (lin & 7) << 3;
            size_t idx = (size_t)(bj + rr)*Nn + bi + cb;
            float4 d0 = *(const float4*)&dist[idx];
            float4 d1 = *(const float4*)&dist[idx + 4];
            float4 m0 = *(const float4*)&deg[idx];
            float4 m1 = *(const float4*)&deg[idx + 4];
            float sv[8];
            #pragma unroll
            for (int k = 0; k < 8; k++) sv[k] = st[(cb + k)*65 + rr];
            float4 o0 = make_float4(sv[0]*(-d0.x)*m0.x, sv[1]*(-d0.y)*m0.y,
                                    sv[2]*(-d0.z)*m0.z, sv[3]*(-d0.w)*m0.w);
            float4 o1 = make_float4(sv[4]*(-d1.x)*m1.x, sv[5]*(-d1.y)*m1.y,
                                    sv[6]*(-d1.z)*m1.z, sv[7]*(-d1.w)*m1.w);
            *(float4*)&g_C[idx]     = o0;
            *(float4*)&g_C[idx + 4] = o1;
            float s  = ((o0.x+o0.y)+(o0.z+o0.w)) + ((o1.x+o1.y)+(o1.z+o1.w));
            float s2 = fmaf(o0.x,o0.x, fmaf(o0.y,o0.y, fmaf(o0.z,o0.z, fmaf(o0.w,o0.w,
                       fmaf(o1.x,o1.x, fmaf(o1.y,o1.y, fmaf(o1.z,o1.z, o1.w*o1.w)))))));
            #pragma unroll
            for (int off = 4; off > 0; off >>= 1) {
                s  += __shfl_down_sync(0xffffffffu, s,  off, 8);
                s2 += __shfl_down_sync(0xffffffffu, s2, off, 8);
            }
            if ((tid & 7) == 0) {
                g_Sp[(size_t)a*Nn + bj + rr]  = s;
                g_S2p[(size_t)a*Nn + bj + rr] = s2;
            }
        }
    }
}

// ---------------- finish LN stats from partials ----------------
__global__ void rn_stats2_kernel() {
    int i = blockIdx.x*256 + threadIdx.x;   // < Nn
    float s = 0.f, s2 = 0.f;
    #pragma unroll
    for (int c = 0; c < 32; c++) {
        s  += g_Sp[(size_t)c*Nn + i];
        s2 += g_S2p[(size_t)c*Nn + i];
    }
    float mean = s * (1.f/Nn);
    float var  = s2 * (1.f/Nn) - mean*mean;
    g_mu[i] = mean;
    g_rs[i] = rsqrtf(var + 1e-5f);
}

// ---------------- out = norm(C) + norm(C)^T  (symmetric: compute once, write twice) ----------------
__global__ void symadd_kernel(float* __restrict__ outC) {
    int t = blockIdx.x;
    int a = 0;
    while (t >= 64 - a) { t -= 64 - a; a++; }
    int b = a + t;   // a <= b, 32x32 blocks
    __shared__ float tA[32][33], tB[32][33], tV[32][33];
    int tx = threadIdx.x, ty = threadIdx.y;
    #pragma unroll
    for (int r = 0; r < 32; r += 8) {
        tA[ty + r][tx] = g_C[(size_t)(a*32 + ty + r)*Nn + b*32 + tx];
        tB[ty + r][tx] = g_C[(size_t)(b*32 + ty + r)*Nn + a*32 + tx];
    }
    int j = b*32 + tx;
    float muj = g_mu[j], rsj = g_rs[j];
    __syncthreads();
    #pragma unroll
    for (int r = 0; r < 32; r += 8) {
        int i = a*32 + ty + r;
        float v = (tA[ty + r][tx] - g_mu[i])*g_rs[i] + (tB[tx][ty + r] - muj)*rsj;
        outC[(size_t)i*Nn + j] = v;
        tV[ty + r][tx] = v;
    }
    if (a != b) {
        __syncthreads();
        #pragma unroll
        for (int r = 0; r < 32; r += 8)
            outC[(size_t)(b*32 + ty + r)*Nn + a*32 + tx] = tV[tx][ty + r];
    }
}

extern "C" void kernel_launch(void* const* d_in, const int* in_sizes, int n_in,
                              void* d_out, int out_size) {
    const float* X    = (const float*)d_in[0];
    const float* dist = (const float*)d_in[1];
    const float* bond = (const float*)d_in[2];
    const float* deg  = (const float*)d_in[4];
    const float* Wq   = (const float*)d_in[5];
    const float* Wk   = (const float*)d_in[6];
    const float* Wv   = (const float*)d_in[7];
    const float* wb   = (const float*)d_in[8];
    const float* wbc  = (const float*)d_in[9];
    const float* wg   = (const float*)d_in[10];
    float* out  = (float*)d_out;
    float* outU = out;
    float* outC = out + Nn*Fd;

    // streams: s2 = gemm_v, s3 = attention half-1; main = attention half-0 + tail
    cudaStream_t s2, s3;
    cudaStreamCreateWithFlags(&s2, cudaStreamNonBlocking);
    cudaStreamCreateWithFlags(&s3, cudaStreamNonBlocking);
    cudaEvent_t evFork, evJ2, evJ3;
    cudaEventCreateWithFlags(&evFork, cudaEventDisableTiming);
    cudaEventCreateWithFlags(&evJ2, cudaEventDisableTiming);
    cudaEventCreateWithFlags(&evJ3, cudaEventDisableTiming);

    qk_kernel<<<Nn, 256>>>(X, Wq, Wk);
    cudaEventRecord(evFork, 0);
    cudaStreamWaitEvent(s2, evFork, 0);
    cudaStreamWaitEvent(s3, evFork, 0);

    gemm_v_kernel<<<dim3(Fd/64, Nn/64), 256, 0, s2>>>(X, Wv);
    cudaEventRecord(evJ2, s2);

    // attention half-1 on s3 (columns [1024, 2048))
    colz_kernel<<<dim3(8, ICP), 128, 0, s3>>>(bond, dist, deg, wb, wbc, wg, 1024);
    zred1_kernel<<<dim3(NH/512, 16), 256, 0, s3>>>(NH/2);
    zred2_kernel<<<NH/512, 256, 0, s3>>>(NH/2);
    attnp_kernel<<<dim3(2, 256), 256, 0, s3>>>(bond, dist, deg, wb, wbc, wg, 1024);
    cudaEventRecord(evJ3, s3);

    // attention half-0 on main (columns [0, 1024))
    colz_kernel<<<dim3(8, ICP), 128>>>(bond, dist, deg, wb, wbc, wg, 0);
    zred1_kernel<<<dim3(NH/512, 16), 256>>>(0);
    zred2_kernel<<<NH/512, 256>>>(0);
    attnp_kernel<<<dim3(2, 256), 256>>>(bond, dist, deg, wb, wbc, wg, 0);

    cudaStreamWaitEvent(0, evJ2, 0);
    cudaStreamWaitEvent(0, evJ3, 0);
    gemm_pv_mma<<<dim3(Fd/64, Nn/64), 256>>>(outU);
    sim_mma<<<32*33/2, 256>>>(dist, deg);
    rn_stats2_kernel<<<Nn/256, 256>>>();
    symadd_kernel<<<64*65/2, dim3(32, 8)>>>(outC);

    cudaEventDestroy(evFork);
    cudaEventDestroy(evJ2);
    cudaEventDestroy(evJ3);
    cudaStreamDestroy(s2);
    cudaStreamDestroy(s3);
}